// round 1
// baseline (speedup 1.0000x reference)
#include <cuda_runtime.h>
#include <math.h>

#define B 2
#define S 2048
#define D 1024
#define H 16
#define DH 64
#define BS (B*S)

// Scratch (allocation-free rule: __device__ globals)
__device__ float g_Q[B*H*S*DH];   // [b*H+h][s][e]
__device__ float g_K[B*H*S*DH];
__device__ float g_V[B*H*S*DH];
__device__ float g_O[BS*D];       // attention output, [b*S+s][h*DH+e]

// ---------------------------------------------------------------------------
// QKV projection: per head h, C[4096,64] = X[4096,1024] @ W_h[1024,64]
// BM=128, BN=64, BK=16, 256 threads, 8x4 register tile per thread.
// grid = (BS/128, H, 3)  z: 0=Q 1=K 2=V
// ---------------------------------------------------------------------------
__global__ void qkv_kernel(const float* __restrict__ X,
                           const float* __restrict__ Wq,
                           const float* __restrict__ Wk,
                           const float* __restrict__ Wv) {
    const int h = blockIdx.y;
    const int z = blockIdx.z;
    const float* W = (z == 0) ? Wq : (z == 1) ? Wk : Wv;
    W += (size_t)h * D * DH;
    float* Out = (z == 0) ? g_Q : (z == 1) ? g_K : g_V;

    const int row0 = blockIdx.x * 128;
    const int tid = threadIdx.x;
    const int ty = tid >> 4;   // 0..15
    const int tx = tid & 15;   // 0..15

    __shared__ float As[16][132];  // [k][m], padded
    __shared__ float Bs[16][64];   // [k][n]

    float acc[8][4];
    #pragma unroll
    for (int i = 0; i < 8; i++)
        #pragma unroll
        for (int j = 0; j < 4; j++) acc[i][j] = 0.f;

    for (int k0 = 0; k0 < D; k0 += 16) {
        // A tile: 128x16 = 512 float4
        #pragma unroll
        for (int t = 0; t < 2; t++) {
            int f = tid + t * 256;
            int r = f >> 2;
            int c4 = (f & 3) * 4;
            float4 v = *reinterpret_cast<const float4*>(&X[(size_t)(row0 + r) * D + k0 + c4]);
            As[c4 + 0][r] = v.x;
            As[c4 + 1][r] = v.y;
            As[c4 + 2][r] = v.z;
            As[c4 + 3][r] = v.w;
        }
        // B tile: 16x64 = 256 float4
        {
            int r = tid >> 4;
            int c4 = (tid & 15) * 4;
            *reinterpret_cast<float4*>(&Bs[r][c4]) =
                *reinterpret_cast<const float4*>(&W[(size_t)(k0 + r) * DH + c4]);
        }
        __syncthreads();
        #pragma unroll
        for (int k = 0; k < 16; k++) {
            float4 a0 = *reinterpret_cast<const float4*>(&As[k][ty * 8]);
            float4 a1 = *reinterpret_cast<const float4*>(&As[k][ty * 8 + 4]);
            float4 bv = *reinterpret_cast<const float4*>(&Bs[k][tx * 4]);
            float a[8] = {a0.x, a0.y, a0.z, a0.w, a1.x, a1.y, a1.z, a1.w};
            float b[4] = {bv.x, bv.y, bv.z, bv.w};
            #pragma unroll
            for (int i = 0; i < 8; i++)
                #pragma unroll
                for (int j = 0; j < 4; j++)
                    acc[i][j] += a[i] * b[j];
        }
        __syncthreads();
    }
    #pragma unroll
    for (int i = 0; i < 8; i++) {
        int m = row0 + ty * 8 + i;
        int bb = m / S, ss = m % S;
        float4 v = make_float4(acc[i][0], acc[i][1], acc[i][2], acc[i][3]);
        *reinterpret_cast<float4*>(&Out[((size_t)(bb * H + h) * S + ss) * DH + tx * 4]) = v;
    }
}

// ---------------------------------------------------------------------------
// Flash attention, fp32. One block = 64 query rows of one (b,h).
// 256 threads as (ty,tx)=16x16. Scores: rows r=ty*4+i, cols c=j*16+tx.
// Online softmax with 16-lane shuffle row-reductions.
// grid = (S/64, B*H), dyn smem = 4 * 64 * 68 * 4 bytes
// ---------------------------------------------------------------------------
__global__ void attn_kernel() {
    const int qt = blockIdx.x;
    const int bh = blockIdx.y;
    const float* Qg = g_Q + (size_t)bh * S * DH + (size_t)qt * 64 * DH;
    const float* Kg = g_K + (size_t)bh * S * DH;
    const float* Vg = g_V + (size_t)bh * S * DH;

    extern __shared__ float sm[];
    float (*Qs)[68] = (float(*)[68])(sm);
    float (*Ks)[68] = (float(*)[68])(sm + 64 * 68);
    float (*Vs)[68] = (float(*)[68])(sm + 2 * 64 * 68);
    float (*Ps)[68] = (float(*)[68])(sm + 3 * 64 * 68);

    const int tid = threadIdx.x;
    const int ty = tid >> 4;
    const int tx = tid & 15;

    // Load Q tile, pre-scaled by 1/sqrt(D) = 1/32
    #pragma unroll
    for (int t = 0; t < 4; t++) {
        int f = tid + t * 256;
        int r = f >> 4;
        int c4 = (f & 15) * 4;
        float4 v = *reinterpret_cast<const float4*>(&Qg[(size_t)r * DH + c4]);
        v.x *= 0.03125f; v.y *= 0.03125f; v.z *= 0.03125f; v.w *= 0.03125f;
        *reinterpret_cast<float4*>(&Qs[r][c4]) = v;
    }

    float m_i[4], l_i[4], acc[4][4];
    #pragma unroll
    for (int i = 0; i < 4; i++) {
        m_i[i] = -1e30f;
        l_i[i] = 0.f;
        #pragma unroll
        for (int j = 0; j < 4; j++) acc[i][j] = 0.f;
    }

    for (int kt = 0; kt < S / 64; kt++) {
        __syncthreads();  // protect Ks/Vs/Ps from prior iteration
        #pragma unroll
        for (int t = 0; t < 4; t++) {
            int f = tid + t * 256;
            int r = f >> 4;
            int c4 = (f & 15) * 4;
            *reinterpret_cast<float4*>(&Ks[r][c4]) =
                *reinterpret_cast<const float4*>(&Kg[((size_t)kt * 64 + r) * DH + c4]);
            *reinterpret_cast<float4*>(&Vs[r][c4]) =
                *reinterpret_cast<const float4*>(&Vg[((size_t)kt * 64 + r) * DH + c4]);
        }
        __syncthreads();

        // S = Q K^T (Q already scaled)
        float s[4][4];
        #pragma unroll
        for (int i = 0; i < 4; i++)
            #pragma unroll
            for (int j = 0; j < 4; j++) s[i][j] = 0.f;

        #pragma unroll 4
        for (int k = 0; k < 64; k += 4) {
            float4 q[4], kk[4];
            #pragma unroll
            for (int i = 0; i < 4; i++) q[i] = *reinterpret_cast<const float4*>(&Qs[ty * 4 + i][k]);
            #pragma unroll
            for (int j = 0; j < 4; j++) kk[j] = *reinterpret_cast<const float4*>(&Ks[j * 16 + tx][k]);
            #pragma unroll
            for (int i = 0; i < 4; i++)
                #pragma unroll
                for (int j = 0; j < 4; j++) {
                    s[i][j] += q[i].x * kk[j].x;
                    s[i][j] += q[i].y * kk[j].y;
                    s[i][j] += q[i].z * kk[j].z;
                    s[i][j] += q[i].w * kk[j].w;
                }
        }

        // Online softmax per row (row group = 16 lanes sharing ty)
        #pragma unroll
        for (int i = 0; i < 4; i++) {
            float mx = fmaxf(fmaxf(s[i][0], s[i][1]), fmaxf(s[i][2], s[i][3]));
            #pragma unroll
            for (int o = 8; o >= 1; o >>= 1)
                mx = fmaxf(mx, __shfl_xor_sync(0xffffffffu, mx, o));
            float m_new = fmaxf(m_i[i], mx);
            float corr = __expf(m_i[i] - m_new);
            float p0 = __expf(s[i][0] - m_new);
            float p1 = __expf(s[i][1] - m_new);
            float p2 = __expf(s[i][2] - m_new);
            float p3 = __expf(s[i][3] - m_new);
            float rsum = p0 + p1 + p2 + p3;
            #pragma unroll
            for (int o = 8; o >= 1; o >>= 1)
                rsum += __shfl_xor_sync(0xffffffffu, rsum, o);
            l_i[i] = l_i[i] * corr + rsum;
            m_i[i] = m_new;
            #pragma unroll
            for (int j = 0; j < 4; j++) acc[i][j] *= corr;
            Ps[ty * 4 + i][0 * 16 + tx] = p0;
            Ps[ty * 4 + i][1 * 16 + tx] = p1;
            Ps[ty * 4 + i][2 * 16 + tx] = p2;
            Ps[ty * 4 + i][3 * 16 + tx] = p3;
        }
        __syncthreads();

        // acc += P @ V  (output cols e = j*16+tx)
        #pragma unroll 8
        for (int c = 0; c < 64; c++) {
            float v[4];
            #pragma unroll
            for (int j = 0; j < 4; j++) v[j] = Vs[c][j * 16 + tx];
            #pragma unroll
            for (int i = 0; i < 4; i++) {
                float pv = Ps[ty * 4 + i][c];
                #pragma unroll
                for (int j = 0; j < 4; j++) acc[i][j] += pv * v[j];
            }
        }
    }

    // Epilogue: normalize and scatter to g_O[b*S+s][h*DH+e]
    const int bb = bh / H, hh = bh % H;
    #pragma unroll
    for (int i = 0; i < 4; i++) {
        float inv = 1.f / l_i[i];
        int ss = qt * 64 + ty * 4 + i;
        float* o = &g_O[((size_t)bb * S + ss) * D + hh * DH];
        #pragma unroll
        for (int j = 0; j < 4; j++)
            o[j * 16 + tx] = acc[i][j] * inv;
    }
}

// ---------------------------------------------------------------------------
// Output projection: out[4096,1024] = g_O @ Wo + bo
// Same tiling as qkv_kernel; grid = (BS/128, D/64)
// ---------------------------------------------------------------------------
__global__ void out_kernel(const float* __restrict__ Wo,
                           const float* __restrict__ bo,
                           float* __restrict__ out) {
    const int row0 = blockIdx.x * 128;
    const int n0 = blockIdx.y * 64;
    const int tid = threadIdx.x;
    const int ty = tid >> 4;
    const int tx = tid & 15;

    __shared__ float As[16][132];
    __shared__ float Bs[16][64];

    float acc[8][4];
    #pragma unroll
    for (int i = 0; i < 8; i++)
        #pragma unroll
        for (int j = 0; j < 4; j++) acc[i][j] = 0.f;

    for (int k0 = 0; k0 < D; k0 += 16) {
        #pragma unroll
        for (int t = 0; t < 2; t++) {
            int f = tid + t * 256;
            int r = f >> 2;
            int c4 = (f & 3) * 4;
            float4 v = *reinterpret_cast<const float4*>(&g_O[(size_t)(row0 + r) * D + k0 + c4]);
            As[c4 + 0][r] = v.x;
            As[c4 + 1][r] = v.y;
            As[c4 + 2][r] = v.z;
            As[c4 + 3][r] = v.w;
        }
        {
            int r = tid >> 4;
            int c4 = (tid & 15) * 4;
            *reinterpret_cast<float4*>(&Bs[r][c4]) =
                *reinterpret_cast<const float4*>(&Wo[(size_t)(k0 + r) * D + n0 + c4]);
        }
        __syncthreads();
        #pragma unroll
        for (int k = 0; k < 16; k++) {
            float4 a0 = *reinterpret_cast<const float4*>(&As[k][ty * 8]);
            float4 a1 = *reinterpret_cast<const float4*>(&As[k][ty * 8 + 4]);
            float4 bv = *reinterpret_cast<const float4*>(&Bs[k][tx * 4]);
            float a[8] = {a0.x, a0.y, a0.z, a0.w, a1.x, a1.y, a1.z, a1.w};
            float b[4] = {bv.x, bv.y, bv.z, bv.w};
            #pragma unroll
            for (int i = 0; i < 8; i++)
                #pragma unroll
                for (int j = 0; j < 4; j++)
                    acc[i][j] += a[i] * b[j];
        }
        __syncthreads();
    }

    float4 bias = *reinterpret_cast<const float4*>(&bo[n0 + tx * 4]);
    #pragma unroll
    for (int i = 0; i < 8; i++) {
        int m = row0 + ty * 8 + i;
        float4 v = make_float4(acc[i][0] + bias.x, acc[i][1] + bias.y,
                               acc[i][2] + bias.z, acc[i][3] + bias.w);
        *reinterpret_cast<float4*>(&out[(size_t)m * D + n0 + tx * 4]) = v;
    }
}

extern "C" void kernel_launch(void* const* d_in, const int* in_sizes, int n_in,
                              void* d_out, int out_size) {
    const float* X  = (const float*)d_in[0];
    const float* Wq = (const float*)d_in[1];
    const float* Wk = (const float*)d_in[2];
    const float* Wv = (const float*)d_in[3];
    const float* Wo = (const float*)d_in[4];
    const float* bo = (const float*)d_in[5];
    float* out = (float*)d_out;

    qkv_kernel<<<dim3(BS / 128, H, 3), 256>>>(X, Wq, Wk, Wv);

    const int attn_smem = 4 * 64 * 68 * (int)sizeof(float);  // 69632 B
    cudaFuncSetAttribute(attn_kernel, cudaFuncAttributeMaxDynamicSharedMemorySize, attn_smem);
    attn_kernel<<<dim3(S / 64, B * H), 256, attn_smem>>>();

    out_kernel<<<dim3(BS / 128, D / 64), 256>>>(Wo, bo, out);
}

// round 3
// speedup vs baseline: 2.5550x; 2.5550x over previous
#include <cuda_runtime.h>
#include <cstdint>

#define B 2
#define S 2048
#define D 1024
#define H 16
#define DH 64
#define BS (B*S)

// Scratch (allocation-free rule: __device__ globals)
__device__ float g_Q[B*H*S*DH];   // [b*H+h][s][e]
__device__ float g_K[B*H*S*DH];
__device__ float g_V[B*H*S*DH];
__device__ float g_O[BS*D];       // attention output, [b*S+s][h*DH+e]

__device__ __forceinline__ uint32_t cvt_tf32(float x) {
    uint32_t r;
    asm("cvt.rna.tf32.f32 %0, %1;" : "=r"(r) : "f"(x));
    return r;
}
__device__ __forceinline__ float tf32f(float x) {
    return __uint_as_float(cvt_tf32(x));
}

// mma.sync m16n8k8 tf32 (sm_80 baseline feature — works at compute_103 PTX)
#define MMA_TF32(c, a, b)                                                   \
    asm volatile(                                                           \
        "mma.sync.aligned.m16n8k8.row.col.f32.tf32.tf32.f32 "               \
        "{%0,%1,%2,%3}, {%4,%5,%6,%7}, {%8,%9}, {%0,%1,%2,%3};"             \
        : "+f"((c)[0]), "+f"((c)[1]), "+f"((c)[2]), "+f"((c)[3])            \
        : "r"((a)[0]), "r"((a)[1]), "r"((a)[2]), "r"((a)[3]),               \
          "r"((b)[0]), "r"((b)[1]))

// ===========================================================================
// GEMM via mma.sync tf32:  C[4096, N] = A[4096,1024] @ Wbig[1024, N]
//   mode 0 (QKV): Wbig = [Wq|Wk|Wv] column blocks; out scattered to g_Q/K/V
//   mode 1 (OUT): Wbig = Wo; A = g_O; out = Cout + bias
// CTA tile 128x128, BK=16, 8 warps in 2x4 -> warp tile 64x32.
// ===========================================================================
__global__ __launch_bounds__(256, 2) void gemm_mma(
    const float* __restrict__ X,
    const float* __restrict__ W0,
    const float* __restrict__ W1,
    const float* __restrict__ W2,
    const float* __restrict__ bias,
    float* __restrict__ Cout,
    int mode)
{
    __shared__ float As[128][20];   // [m][k] pad->conflict-free frag loads
    __shared__ float Bs[128][20];   // [n][k]

    const int tid = threadIdx.x;
    const int wid = tid >> 5;
    const int lane = tid & 31;
    const int j = lane & 3;          // lane % 4
    const int r4 = lane >> 2;        // lane / 4
    const int wm = wid >> 2;         // 0..1
    const int wn = wid & 3;          // 0..3
    const int row0 = blockIdx.x * 128;
    const int n0 = blockIdx.y * 128;

    const float* Ag = (mode == 0) ? X : g_O;

    // B gather pointer: column n of conceptual Wbig
    const int nloc = tid & 127;
    const int kh = tid >> 7;  // 0/1 -> which 8-k half this thread stages
    const float* colp;
    int strideK;
    if (mode == 0) {
        int ng = n0 + nloc;
        int z = ng >> 10, rr = ng & 1023;
        const float* Wz = (z == 0) ? W0 : (z == 1) ? W1 : W2;
        colp = Wz + (size_t)(rr >> 6) * (D * DH) + (rr & 63);
        strideK = DH;
    } else {
        colp = W0 + n0 + nloc;
        strideK = D;
    }

    float c[4][4][4];
    #pragma unroll
    for (int mt = 0; mt < 4; mt++)
        #pragma unroll
        for (int nt = 0; nt < 4; nt++)
            #pragma unroll
            for (int q = 0; q < 4; q++) c[mt][nt][q] = 0.f;

    for (int k0 = 0; k0 < D; k0 += 16) {
        // --- stage A: 128 rows x 16 k ---
        #pragma unroll
        for (int i = 0; i < 2; i++) {
            int f = tid + i * 256;
            int m = f >> 2, kq = f & 3;
            float4 v = *reinterpret_cast<const float4*>(
                Ag + (size_t)(row0 + m) * D + k0 + kq * 4);
            float4 t = make_float4(tf32f(v.x), tf32f(v.y), tf32f(v.z), tf32f(v.w));
            *reinterpret_cast<float4*>(&As[m][kq * 4]) = t;
        }
        // --- stage B: 128 cols x 16 k (gather strided) ---
        {
            const float* p = colp + (size_t)(k0 + kh * 8) * strideK;
            float4 lo = make_float4(tf32f(p[0]), tf32f(p[(size_t)strideK]),
                                    tf32f(p[2 * (size_t)strideK]), tf32f(p[3 * (size_t)strideK]));
            float4 hi = make_float4(tf32f(p[4 * (size_t)strideK]), tf32f(p[5 * (size_t)strideK]),
                                    tf32f(p[6 * (size_t)strideK]), tf32f(p[7 * (size_t)strideK]));
            *reinterpret_cast<float4*>(&Bs[nloc][kh * 8]) = lo;
            *reinterpret_cast<float4*>(&Bs[nloc][kh * 8 + 4]) = hi;
        }
        __syncthreads();

        #pragma unroll
        for (int ks = 0; ks < 2; ks++) {
            const int kb = ks * 8;
            uint32_t a[4][4], b[4][2];
            #pragma unroll
            for (int mt = 0; mt < 4; mt++) {
                int m0 = wm * 64 + mt * 16 + r4;
                a[mt][0] = __float_as_uint(As[m0][kb + j]);
                a[mt][1] = __float_as_uint(As[m0 + 8][kb + j]);
                a[mt][2] = __float_as_uint(As[m0][kb + j + 4]);
                a[mt][3] = __float_as_uint(As[m0 + 8][kb + j + 4]);
            }
            #pragma unroll
            for (int nt = 0; nt < 4; nt++) {
                int n = wn * 32 + nt * 8 + r4;
                b[nt][0] = __float_as_uint(Bs[n][kb + j]);
                b[nt][1] = __float_as_uint(Bs[n][kb + j + 4]);
            }
            #pragma unroll
            for (int mt = 0; mt < 4; mt++)
                #pragma unroll
                for (int nt = 0; nt < 4; nt++)
                    MMA_TF32(c[mt][nt], a[mt], b[nt]);
        }
        __syncthreads();
    }

    // --- epilogue ---
    #pragma unroll
    for (int mt = 0; mt < 4; mt++) {
        int m_lo = row0 + wm * 64 + mt * 16 + r4;
        int m_hi = m_lo + 8;
        #pragma unroll
        for (int nt = 0; nt < 4; nt++) {
            int n = n0 + wn * 32 + nt * 8 + 2 * j;
            if (mode == 0) {
                int z = n >> 10, rr = n & 1023;
                int h = rr >> 6, e0 = rr & 63;
                float* Out = (z == 0) ? g_Q : (z == 1) ? g_K : g_V;
                int bb_lo = m_lo >> 11, ss_lo = m_lo & (S - 1);
                int bb_hi = m_hi >> 11, ss_hi = m_hi & (S - 1);
                *reinterpret_cast<float2*>(
                    Out + ((size_t)(bb_lo * H + h) * S + ss_lo) * DH + e0) =
                    make_float2(c[mt][nt][0], c[mt][nt][1]);
                *reinterpret_cast<float2*>(
                    Out + ((size_t)(bb_hi * H + h) * S + ss_hi) * DH + e0) =
                    make_float2(c[mt][nt][2], c[mt][nt][3]);
            } else {
                float2 bv = *reinterpret_cast<const float2*>(bias + n);
                *reinterpret_cast<float2*>(Cout + (size_t)m_lo * D + n) =
                    make_float2(c[mt][nt][0] + bv.x, c[mt][nt][1] + bv.y);
                *reinterpret_cast<float2*>(Cout + (size_t)m_hi * D + n) =
                    make_float2(c[mt][nt][2] + bv.x, c[mt][nt][3] + bv.y);
            }
        }
    }
}

// ===========================================================================
// Flash attention via mma.sync tf32.
// CTA: 128 q-rows of one (b,h); 8 warps x 16 rows. K-tile = 64.
// Per warp: S[16x64] = Q K^T (mma), online softmax in C-frag layout,
// P->smem->A-frag reshape, O[16x64] += P V (mma).
// smem: Ks[64][72], Vs[64][72], Ps[128][72] (Q staging reuses Ps).
// ===========================================================================
__global__ __launch_bounds__(256, 2) void attn_mma() {
    extern __shared__ float sm[];
    float (*Ks)[72] = (float(*)[72])(sm);
    float (*Vs)[72] = (float(*)[72])(sm + 64 * 72);
    float (*Ps)[72] = (float(*)[72])(sm + 128 * 72);

    const int qt = blockIdx.x;
    const int bh = blockIdx.y;
    const float* Qg = g_Q + (size_t)bh * S * DH + (size_t)qt * 128 * DH;
    const float* Kg = g_K + (size_t)bh * S * DH;
    const float* Vg = g_V + (size_t)bh * S * DH;

    const int tid = threadIdx.x;
    const int wid = tid >> 5;
    const int lane = tid & 31;
    const int j = lane & 3;
    const int r4 = lane >> 2;
    const int mrow = wid * 16 + r4;   // this lane's low row in warp tile

    // --- stage Q (scaled 1/32, tf32) into Ps ---
    #pragma unroll
    for (int i = 0; i < 8; i++) {
        int f = tid + i * 256;
        int m = f >> 4, cc = (f & 15) * 4;
        float4 v = *reinterpret_cast<const float4*>(Qg + (size_t)m * DH + cc);
        float4 t = make_float4(tf32f(v.x * 0.03125f), tf32f(v.y * 0.03125f),
                               tf32f(v.z * 0.03125f), tf32f(v.w * 0.03125f));
        *reinterpret_cast<float4*>(&Ps[m][cc]) = t;
    }
    __syncthreads();

    // --- extract persistent Q fragments ---
    uint32_t qf[8][4];
    #pragma unroll
    for (int ks = 0; ks < 8; ks++) {
        qf[ks][0] = __float_as_uint(Ps[mrow][8 * ks + j]);
        qf[ks][1] = __float_as_uint(Ps[mrow + 8][8 * ks + j]);
        qf[ks][2] = __float_as_uint(Ps[mrow][8 * ks + j + 4]);
        qf[ks][3] = __float_as_uint(Ps[mrow + 8][8 * ks + j + 4]);
    }

    float oacc[8][4];
    #pragma unroll
    for (int nt = 0; nt < 8; nt++)
        #pragma unroll
        for (int q = 0; q < 4; q++) oacc[nt][q] = 0.f;
    float m_lo = -1e30f, m_hi = -1e30f, l_lo = 0.f, l_hi = 0.f;

    for (int kt = 0; kt < S / 64; kt++) {
        __syncthreads();   // prior iter done with Ks/Vs
        // --- stage K, V tiles (tf32) ---
        #pragma unroll
        for (int i = 0; i < 4; i++) {
            int f = tid + i * 256;
            int r = f >> 4, cc = (f & 15) * 4;
            float4 kv = *reinterpret_cast<const float4*>(
                Kg + ((size_t)kt * 64 + r) * DH + cc);
            float4 vv = *reinterpret_cast<const float4*>(
                Vg + ((size_t)kt * 64 + r) * DH + cc);
            *reinterpret_cast<float4*>(&Ks[r][cc]) =
                make_float4(tf32f(kv.x), tf32f(kv.y), tf32f(kv.z), tf32f(kv.w));
            *reinterpret_cast<float4*>(&Vs[r][cc]) =
                make_float4(tf32f(vv.x), tf32f(vv.y), tf32f(vv.z), tf32f(vv.w));
        }
        __syncthreads();

        // --- S = Q K^T ---
        float s[8][4];
        #pragma unroll
        for (int nt = 0; nt < 8; nt++)
            #pragma unroll
            for (int q = 0; q < 4; q++) s[nt][q] = 0.f;

        #pragma unroll
        for (int ks = 0; ks < 8; ks++) {
            #pragma unroll
            for (int nt = 0; nt < 8; nt++) {
                uint32_t b[2];
                b[0] = __float_as_uint(Ks[8 * nt + r4][8 * ks + j]);
                b[1] = __float_as_uint(Ks[8 * nt + r4][8 * ks + j + 4]);
                MMA_TF32(s[nt], qf[ks], b);
            }
        }

        // --- online softmax (rows r4 and r4+8 of warp tile) ---
        float mx_lo = -1e30f, mx_hi = -1e30f;
        #pragma unroll
        for (int nt = 0; nt < 8; nt++) {
            mx_lo = fmaxf(mx_lo, fmaxf(s[nt][0], s[nt][1]));
            mx_hi = fmaxf(mx_hi, fmaxf(s[nt][2], s[nt][3]));
        }
        mx_lo = fmaxf(mx_lo, __shfl_xor_sync(0xffffffffu, mx_lo, 1));
        mx_lo = fmaxf(mx_lo, __shfl_xor_sync(0xffffffffu, mx_lo, 2));
        mx_hi = fmaxf(mx_hi, __shfl_xor_sync(0xffffffffu, mx_hi, 1));
        mx_hi = fmaxf(mx_hi, __shfl_xor_sync(0xffffffffu, mx_hi, 2));

        float mn_lo = fmaxf(m_lo, mx_lo);
        float mn_hi = fmaxf(m_hi, mx_hi);
        float corr_lo = __expf(m_lo - mn_lo);
        float corr_hi = __expf(m_hi - mn_hi);
        m_lo = mn_lo; m_hi = mn_hi;

        float rs_lo = 0.f, rs_hi = 0.f;
        #pragma unroll
        for (int nt = 0; nt < 8; nt++) {
            s[nt][0] = __expf(s[nt][0] - mn_lo);
            s[nt][1] = __expf(s[nt][1] - mn_lo);
            s[nt][2] = __expf(s[nt][2] - mn_hi);
            s[nt][3] = __expf(s[nt][3] - mn_hi);
            rs_lo += s[nt][0] + s[nt][1];
            rs_hi += s[nt][2] + s[nt][3];
        }
        rs_lo += __shfl_xor_sync(0xffffffffu, rs_lo, 1);
        rs_lo += __shfl_xor_sync(0xffffffffu, rs_lo, 2);
        rs_hi += __shfl_xor_sync(0xffffffffu, rs_hi, 1);
        rs_hi += __shfl_xor_sync(0xffffffffu, rs_hi, 2);
        l_lo = l_lo * corr_lo + rs_lo;
        l_hi = l_hi * corr_hi + rs_hi;

        #pragma unroll
        for (int nt = 0; nt < 8; nt++) {
            oacc[nt][0] *= corr_lo; oacc[nt][1] *= corr_lo;
            oacc[nt][2] *= corr_hi; oacc[nt][3] *= corr_hi;
        }

        // --- P -> smem (per-warp private rows), reshape to A-frags ---
        #pragma unroll
        for (int nt = 0; nt < 8; nt++) {
            int col = 8 * nt + 2 * j;
            Ps[mrow][col]     = tf32f(s[nt][0]);
            Ps[mrow][col + 1] = tf32f(s[nt][1]);
            Ps[mrow + 8][col]     = tf32f(s[nt][2]);
            Ps[mrow + 8][col + 1] = tf32f(s[nt][3]);
        }
        __syncwarp();

        // --- O += P @ V ---
        #pragma unroll
        for (int ks = 0; ks < 8; ks++) {
            uint32_t ap[4];
            ap[0] = __float_as_uint(Ps[mrow][8 * ks + j]);
            ap[1] = __float_as_uint(Ps[mrow + 8][8 * ks + j]);
            ap[2] = __float_as_uint(Ps[mrow][8 * ks + j + 4]);
            ap[3] = __float_as_uint(Ps[mrow + 8][8 * ks + j + 4]);
            #pragma unroll
            for (int nt = 0; nt < 8; nt++) {
                uint32_t b[2];
                b[0] = __float_as_uint(Vs[8 * ks + j][8 * nt + r4]);
                b[1] = __float_as_uint(Vs[8 * ks + j + 4][8 * nt + r4]);
                MMA_TF32(oacc[nt], ap, b);
            }
        }
        __syncwarp();
    }

    // --- epilogue: normalize, scatter to g_O ---
    const float inv_lo = 1.f / l_lo;
    const float inv_hi = 1.f / l_hi;
    const int bb = bh >> 4, hh = bh & 15;
    const int row_lo = qt * 128 + wid * 16 + r4;
    const int row_hi = row_lo + 8;
    #pragma unroll
    for (int nt = 0; nt < 8; nt++) {
        int e = 8 * nt + 2 * j;
        *reinterpret_cast<float2*>(
            g_O + ((size_t)bb * S + row_lo) * D + hh * DH + e) =
            make_float2(oacc[nt][0] * inv_lo, oacc[nt][1] * inv_lo);
        *reinterpret_cast<float2*>(
            g_O + ((size_t)bb * S + row_hi) * D + hh * DH + e) =
            make_float2(oacc[nt][2] * inv_hi, oacc[nt][3] * inv_hi);
    }
}

extern "C" void kernel_launch(void* const* d_in, const int* in_sizes, int n_in,
                              void* d_out, int out_size) {
    const float* X  = (const float*)d_in[0];
    const float* Wq = (const float*)d_in[1];
    const float* Wk = (const float*)d_in[2];
    const float* Wv = (const float*)d_in[3];
    const float* Wo = (const float*)d_in[4];
    const float* bo = (const float*)d_in[5];
    float* out = (float*)d_out;

    // QKV: [4096, 3072] = X @ [Wq|Wk|Wv]
    gemm_mma<<<dim3(BS / 128, 24), 256>>>(X, Wq, Wk, Wv, nullptr, nullptr, 0);

    const int attn_smem = 256 * 72 * (int)sizeof(float);  // 73728 B
    cudaFuncSetAttribute(attn_mma, cudaFuncAttributeMaxDynamicSharedMemorySize, attn_smem);
    attn_mma<<<dim3(S / 128, B * H), 256, attn_smem>>>();

    // OUT: [4096, 1024] = g_O @ Wo + bo
    gemm_mma<<<dim3(BS / 128, 8), 256>>>(X, Wo, nullptr, nullptr, bo, out, 1);
}

// round 5
// speedup vs baseline: 2.6491x; 1.0368x over previous
#include <cuda_runtime.h>
#include <cstdint>

#define B 2
#define S 2048
#define D 1024
#define H 16
#define DH 64
#define BS (B*S)
#define NW 4096   // 3072 qkv cols + 1024 out-proj cols

// Scratch (allocation-free rule: __device__ globals)
__device__ float g_Q[B*H*S*DH];   // [b*H+h][s][e]
__device__ float g_K[B*H*S*DH];
__device__ float g_V[B*H*S*DH];
__device__ float g_O[BS*D];       // attention output, [b*S+s][h*DH+e]
__device__ float g_WT[NW*D];      // transposed weights: row n = col n of [Wq|Wk|Wv|Wo]

__device__ __forceinline__ uint32_t cvt_tf32(float x) {
    uint32_t r;
    asm("cvt.rna.tf32.f32 %0, %1;" : "=r"(r) : "f"(x));
    return r;
}
__device__ __forceinline__ float tf32f(float x) {
    return __uint_as_float(cvt_tf32(x));
}
__device__ __forceinline__ uint32_t smem_u32(const void* p) {
    uint32_t a;
    asm("{ .reg .u64 t; cvta.to.shared.u64 t, %1; cvt.u32.u64 %0, t; }"
        : "=r"(a) : "l"(p));
    return a;
}

#define MMA_TF32(c, a, b)                                                   \
    asm volatile(                                                           \
        "mma.sync.aligned.m16n8k8.row.col.f32.tf32.tf32.f32 "               \
        "{%0,%1,%2,%3}, {%4,%5,%6,%7}, {%8,%9}, {%0,%1,%2,%3};"             \
        : "+f"((c)[0]), "+f"((c)[1]), "+f"((c)[2]), "+f"((c)[3])            \
        : "r"((a)[0]), "r"((a)[1]), "r"((a)[2]), "r"((a)[3]),               \
          "r"((b)[0]), "r"((b)[1]))

#define CP16(dst, src) \
    asm volatile("cp.async.cg.shared.global [%0], [%1], 16;" :: "r"(dst), "l"(src))
#define CP_COMMIT() asm volatile("cp.async.commit_group;" ::: "memory")
#define CP_WAIT1()  asm volatile("cp.async.wait_group 1;" ::: "memory")
#define CP_WAIT0()  asm volatile("cp.async.wait_group 0;" ::: "memory")

// ===========================================================================
// Weight transpose prep: g_WT[n][d] = Wbig[d][n]
// ===========================================================================
__global__ void prep_wt(const float* __restrict__ Wq, const float* __restrict__ Wk,
                        const float* __restrict__ Wv, const float* __restrict__ Wo) {
    __shared__ float t[32][33];
    const int n0 = blockIdx.x * 32;
    const int d0 = blockIdx.y * 32;
    const int tx = threadIdx.x, ty = threadIdx.y;

    #pragma unroll
    for (int k = 0; k < 4; k++) {
        int d = d0 + ty + 8 * k;
        int n = n0 + tx;
        float v;
        if (n < 3072) {
            int z = n >> 10, h = (n >> 6) & 15, e = n & 63;
            const float* Wz = (z == 0) ? Wq : (z == 1) ? Wk : Wv;
            v = Wz[((size_t)h * D + d) * DH + e];
        } else {
            v = Wo[(size_t)d * D + (n - 3072)];
        }
        t[tx][ty + 8 * k] = v;
    }
    __syncthreads();
    #pragma unroll
    for (int k = 0; k < 4; k++) {
        int n = n0 + ty + 8 * k;
        int d = d0 + tx;
        g_WT[(size_t)n * D + d] = t[ty + 8 * k][tx];
    }
}

// ===========================================================================
// Pipelined GEMM: C[4096, 128-block] = A[4096,1024] @ WT^T
// BK=32, 2-stage cp.async double buffer, 8 warps (2x4), warp tile 64x32.
//   mode 0: A = Xg, out scattered to g_Q/g_K/g_V
//   mode 1: A = g_O (resolved ON DEVICE), out = Cout + bias
// dyn smem = 4 * 128*36 * 4 = 73728 B
// ===========================================================================
#define TS (128*36)

__global__ __launch_bounds__(256, 2) void gemm_mma(
    const float* __restrict__ Xg,
    const float* __restrict__ bias,
    float* __restrict__ Cout,
    int nwbase, int mode)
{
    extern __shared__ float sm[];
    const uint32_t sbase = smem_u32(sm);

    const int tid = threadIdx.x;
    const int wid = tid >> 5;
    const int lane = tid & 31;
    const int j = lane & 3;
    const int r4 = lane >> 2;
    const int wm = wid >> 2;
    const int wn = wid & 3;
    const int row0 = blockIdx.x * 128;
    const int n0 = blockIdx.y * 128;

    // IMPORTANT: device-global scratch must be resolved in device code.
    const float* Ag = (mode == 0) ? Xg : (const float*)g_O;

    auto stage = [&](int k0, int buf) {
        const uint32_t ab = sbase + (2 * buf) * TS * 4;
        const uint32_t bb = sbase + (2 * buf + 1) * TS * 4;
        #pragma unroll
        for (int i = 0; i < 4; i++) {
            int f = tid + i * 256;
            int m = f >> 3, kq = (f & 7) * 4;
            CP16(ab + (m * 36 + kq) * 4, Ag + (size_t)(row0 + m) * D + k0 + kq);
            CP16(bb + (m * 36 + kq) * 4, g_WT + (size_t)(nwbase + n0 + m) * D + k0 + kq);
        }
    };

    float c[4][4][4];
    #pragma unroll
    for (int mt = 0; mt < 4; mt++)
        #pragma unroll
        for (int nt = 0; nt < 4; nt++)
            #pragma unroll
            for (int q = 0; q < 4; q++) c[mt][nt][q] = 0.f;

    stage(0, 0);
    CP_COMMIT();

    for (int it = 0; it < 32; it++) {
        if (it < 31) {
            stage((it + 1) * 32, (it + 1) & 1);
            CP_COMMIT();
            CP_WAIT1();
        } else {
            CP_WAIT0();
        }
        __syncthreads();

        const float* Af = sm + (2 * (it & 1)) * TS;
        const float* Bf = sm + (2 * (it & 1) + 1) * TS;
        #pragma unroll
        for (int ks = 0; ks < 4; ks++) {
            const int kb = ks * 8;
            uint32_t a[4][4], b[4][2];
            #pragma unroll
            for (int mt = 0; mt < 4; mt++) {
                int m0 = wm * 64 + mt * 16 + r4;
                a[mt][0] = cvt_tf32(Af[m0 * 36 + kb + j]);
                a[mt][1] = cvt_tf32(Af[(m0 + 8) * 36 + kb + j]);
                a[mt][2] = cvt_tf32(Af[m0 * 36 + kb + j + 4]);
                a[mt][3] = cvt_tf32(Af[(m0 + 8) * 36 + kb + j + 4]);
            }
            #pragma unroll
            for (int nt = 0; nt < 4; nt++) {
                int n = wn * 32 + nt * 8 + r4;
                b[nt][0] = cvt_tf32(Bf[n * 36 + kb + j]);
                b[nt][1] = cvt_tf32(Bf[n * 36 + kb + j + 4]);
            }
            #pragma unroll
            for (int mt = 0; mt < 4; mt++)
                #pragma unroll
                for (int nt = 0; nt < 4; nt++)
                    MMA_TF32(c[mt][nt], a[mt], b[nt]);
        }
        __syncthreads();
    }

    // --- epilogue ---
    #pragma unroll
    for (int mt = 0; mt < 4; mt++) {
        int m_lo = row0 + wm * 64 + mt * 16 + r4;
        int m_hi = m_lo + 8;
        #pragma unroll
        for (int nt = 0; nt < 4; nt++) {
            int n = n0 + wn * 32 + nt * 8 + 2 * j;
            if (mode == 0) {
                int z = n >> 10, rr = n & 1023;
                int h = rr >> 6, e0 = rr & 63;
                float* Out = (z == 0) ? g_Q : (z == 1) ? g_K : g_V;
                int bb_lo = m_lo >> 11, ss_lo = m_lo & (S - 1);
                int bb_hi = m_hi >> 11, ss_hi = m_hi & (S - 1);
                *reinterpret_cast<float2*>(
                    Out + ((size_t)(bb_lo * H + h) * S + ss_lo) * DH + e0) =
                    make_float2(c[mt][nt][0], c[mt][nt][1]);
                *reinterpret_cast<float2*>(
                    Out + ((size_t)(bb_hi * H + h) * S + ss_hi) * DH + e0) =
                    make_float2(c[mt][nt][2], c[mt][nt][3]);
            } else {
                float2 bv = *reinterpret_cast<const float2*>(bias + n);
                *reinterpret_cast<float2*>(Cout + (size_t)m_lo * D + n) =
                    make_float2(c[mt][nt][0] + bv.x, c[mt][nt][1] + bv.y);
                *reinterpret_cast<float2*>(Cout + (size_t)m_hi * D + n) =
                    make_float2(c[mt][nt][2] + bv.x, c[mt][nt][3] + bv.y);
            }
        }
    }
}

// ===========================================================================
// Flash attention, mma.sync tf32, cp.async double-buffered K/V.
// CTA: 128 q-rows of one (b,h); 8 warps x 16 rows; k-tile 64.
// P reshape C-frag -> A-frag via warp shuffles (no smem round trip).
// smem: 2 buffers x (K[64][68] + V[64][68]) = 69632 B
// ===========================================================================
#define KVT (64*68)

__global__ __launch_bounds__(256, 2) void attn_mma() {
    extern __shared__ float sm[];
    const uint32_t sbase = smem_u32(sm);

    const int qt = blockIdx.x;
    const int bh = blockIdx.y;
    const float* Qg = g_Q + (size_t)bh * S * DH + (size_t)qt * 128 * DH;
    const float* Kg = g_K + (size_t)bh * S * DH;
    const float* Vg = g_V + (size_t)bh * S * DH;

    const int tid = threadIdx.x;
    const int wid = tid >> 5;
    const int lane = tid & 31;
    const int j = lane & 3;
    const int r4 = lane >> 2;
    const int mrow = wid * 16 + r4;

    auto stage = [&](int kt, int buf) {
        const uint32_t kb = sbase + buf * (2 * KVT) * 4;
        const uint32_t vb = kb + KVT * 4;
        const float* Kt = Kg + (size_t)kt * 64 * DH;
        const float* Vt = Vg + (size_t)kt * 64 * DH;
        #pragma unroll
        for (int i = 0; i < 4; i++) {
            int f = tid + i * 256;
            int r = f >> 4, sg = (f & 15) * 4;
            CP16(kb + (r * 68 + sg) * 4, Kt + (size_t)r * DH + sg);
            CP16(vb + (r * 68 + sg) * 4, Vt + (size_t)r * DH + sg);
        }
    };

    // --- persistent Q fragments straight from gmem (scaled 1/32, tf32) ---
    uint32_t qf[8][4];
    #pragma unroll
    for (int ks = 0; ks < 8; ks++) {
        qf[ks][0] = cvt_tf32(Qg[(size_t)mrow * DH + 8 * ks + j] * 0.03125f);
        qf[ks][1] = cvt_tf32(Qg[(size_t)(mrow + 8) * DH + 8 * ks + j] * 0.03125f);
        qf[ks][2] = cvt_tf32(Qg[(size_t)mrow * DH + 8 * ks + j + 4] * 0.03125f);
        qf[ks][3] = cvt_tf32(Qg[(size_t)(mrow + 8) * DH + 8 * ks + j + 4] * 0.03125f);
    }

    float oacc[8][4];
    #pragma unroll
    for (int nt = 0; nt < 8; nt++)
        #pragma unroll
        for (int q = 0; q < 4; q++) oacc[nt][q] = 0.f;
    float m_lo = -1e30f, m_hi = -1e30f, l_lo = 0.f, l_hi = 0.f;

    stage(0, 0);
    CP_COMMIT();

    for (int kt = 0; kt < S / 64; kt++) {
        if (kt < S / 64 - 1) {
            stage(kt + 1, (kt + 1) & 1);
            CP_COMMIT();
            CP_WAIT1();
        } else {
            CP_WAIT0();
        }
        __syncthreads();

        const int buf = kt & 1;
        // --- in-place tf32 conversion of the K/V tile (1 cvt per element) ---
        {
            float4* bp = reinterpret_cast<float4*>(sm + buf * (2 * KVT));
            #pragma unroll
            for (int i = 0; i < 9; i++) {
                int x = tid + i * 256;
                if (x < (2 * KVT) / 4) {
                    float4 v = bp[x];
                    v.x = tf32f(v.x); v.y = tf32f(v.y);
                    v.z = tf32f(v.z); v.w = tf32f(v.w);
                    bp[x] = v;
                }
            }
        }
        __syncthreads();

        const float* Kf = sm + buf * (2 * KVT);
        const float* Vf = Kf + KVT;

        // --- S = Q K^T ---
        float s[8][4];
        #pragma unroll
        for (int nt = 0; nt < 8; nt++)
            #pragma unroll
            for (int q = 0; q < 4; q++) s[nt][q] = 0.f;

        #pragma unroll
        for (int ks = 0; ks < 8; ks++) {
            #pragma unroll
            for (int nt = 0; nt < 8; nt++) {
                uint32_t b[2];
                b[0] = __float_as_uint(Kf[(8 * nt + r4) * 68 + 8 * ks + j]);
                b[1] = __float_as_uint(Kf[(8 * nt + r4) * 68 + 8 * ks + j + 4]);
                MMA_TF32(s[nt], qf[ks], b);
            }
        }

        // --- online softmax ---
        float mx_lo = -1e30f, mx_hi = -1e30f;
        #pragma unroll
        for (int nt = 0; nt < 8; nt++) {
            mx_lo = fmaxf(mx_lo, fmaxf(s[nt][0], s[nt][1]));
            mx_hi = fmaxf(mx_hi, fmaxf(s[nt][2], s[nt][3]));
        }
        mx_lo = fmaxf(mx_lo, __shfl_xor_sync(0xffffffffu, mx_lo, 1));
        mx_lo = fmaxf(mx_lo, __shfl_xor_sync(0xffffffffu, mx_lo, 2));
        mx_hi = fmaxf(mx_hi, __shfl_xor_sync(0xffffffffu, mx_hi, 1));
        mx_hi = fmaxf(mx_hi, __shfl_xor_sync(0xffffffffu, mx_hi, 2));

        float mn_lo = fmaxf(m_lo, mx_lo);
        float mn_hi = fmaxf(m_hi, mx_hi);
        float corr_lo = __expf(m_lo - mn_lo);
        float corr_hi = __expf(m_hi - mn_hi);
        m_lo = mn_lo; m_hi = mn_hi;

        float rs_lo = 0.f, rs_hi = 0.f;
        #pragma unroll
        for (int nt = 0; nt < 8; nt++) {
            s[nt][0] = __expf(s[nt][0] - mn_lo);
            s[nt][1] = __expf(s[nt][1] - mn_lo);
            s[nt][2] = __expf(s[nt][2] - mn_hi);
            s[nt][3] = __expf(s[nt][3] - mn_hi);
            rs_lo += s[nt][0] + s[nt][1];
            rs_hi += s[nt][2] + s[nt][3];
        }
        rs_lo += __shfl_xor_sync(0xffffffffu, rs_lo, 1);
        rs_lo += __shfl_xor_sync(0xffffffffu, rs_lo, 2);
        rs_hi += __shfl_xor_sync(0xffffffffu, rs_hi, 1);
        rs_hi += __shfl_xor_sync(0xffffffffu, rs_hi, 2);
        l_lo = l_lo * corr_lo + rs_lo;
        l_hi = l_hi * corr_hi + rs_hi;

        #pragma unroll
        for (int nt = 0; nt < 8; nt++) {
            oacc[nt][0] *= corr_lo; oacc[nt][1] *= corr_lo;
            oacc[nt][2] *= corr_hi; oacc[nt][3] *= corr_hi;
        }

        // --- O += P @ V  (P reshaped C-frag -> A-frag via shuffles) ---
        const int L0 = (r4 << 2) | (j >> 1);
        const int L1 = L0 + 2;
        #pragma unroll
        for (int kk = 0; kk < 8; kk++) {
            uint32_t pc0 = cvt_tf32(s[kk][0]);
            uint32_t pc1 = cvt_tf32(s[kk][1]);
            uint32_t pc2 = cvt_tf32(s[kk][2]);
            uint32_t pc3 = cvt_tf32(s[kk][3]);
            uint32_t ap[4], e, o;
            e = __shfl_sync(0xffffffffu, pc0, L0);
            o = __shfl_sync(0xffffffffu, pc1, L0);
            ap[0] = (j & 1) ? o : e;
            e = __shfl_sync(0xffffffffu, pc2, L0);
            o = __shfl_sync(0xffffffffu, pc3, L0);
            ap[1] = (j & 1) ? o : e;
            e = __shfl_sync(0xffffffffu, pc0, L1);
            o = __shfl_sync(0xffffffffu, pc1, L1);
            ap[2] = (j & 1) ? o : e;
            e = __shfl_sync(0xffffffffu, pc2, L1);
            o = __shfl_sync(0xffffffffu, pc3, L1);
            ap[3] = (j & 1) ? o : e;

            #pragma unroll
            for (int nt = 0; nt < 8; nt++) {
                uint32_t b[2];
                b[0] = __float_as_uint(Vf[(8 * kk + j) * 68 + 8 * nt + r4]);
                b[1] = __float_as_uint(Vf[(8 * kk + j + 4) * 68 + 8 * nt + r4]);
                MMA_TF32(oacc[nt], ap, b);
            }
        }
        __syncthreads();
    }

    // --- epilogue ---
    const float inv_lo = 1.f / l_lo;
    const float inv_hi = 1.f / l_hi;
    const int bb = bh >> 4, hh = bh & 15;
    const int row_lo = qt * 128 + wid * 16 + r4;
    const int row_hi = row_lo + 8;
    #pragma unroll
    for (int nt = 0; nt < 8; nt++) {
        int e = 8 * nt + 2 * j;
        *reinterpret_cast<float2*>(
            g_O + ((size_t)bb * S + row_lo) * D + hh * DH + e) =
            make_float2(oacc[nt][0] * inv_lo, oacc[nt][1] * inv_lo);
        *reinterpret_cast<float2*>(
            g_O + ((size_t)bb * S + row_hi) * D + hh * DH + e) =
            make_float2(oacc[nt][2] * inv_hi, oacc[nt][3] * inv_hi);
    }
}

extern "C" void kernel_launch(void* const* d_in, const int* in_sizes, int n_in,
                              void* d_out, int out_size) {
    const float* X  = (const float*)d_in[0];
    const float* Wq = (const float*)d_in[1];
    const float* Wk = (const float*)d_in[2];
    const float* Wv = (const float*)d_in[3];
    const float* Wo = (const float*)d_in[4];
    const float* bo = (const float*)d_in[5];
    float* out = (float*)d_out;

    prep_wt<<<dim3(NW / 32, D / 32), dim3(32, 8)>>>(Wq, Wk, Wv, Wo);

    const int gemm_smem = 4 * TS * (int)sizeof(float);  // 73728
    cudaFuncSetAttribute(gemm_mma, cudaFuncAttributeMaxDynamicSharedMemorySize, gemm_smem);
    gemm_mma<<<dim3(BS / 128, 24), 256, gemm_smem>>>(X, nullptr, nullptr, 0, 0);

    const int attn_smem = 4 * KVT * (int)sizeof(float);  // 69632
    cudaFuncSetAttribute(attn_mma, cudaFuncAttributeMaxDynamicSharedMemorySize, attn_smem);
    attn_mma<<<dim3(S / 128, B * H), 256, attn_smem>>>();

    // mode 1: A = g_O resolved inside the kernel (NOT passed from host!)
    gemm_mma<<<dim3(BS / 128, 8), 256, gemm_smem>>>(X, bo, out, 3072, 1);
}

// round 6
// speedup vs baseline: 5.6883x; 2.1473x over previous
#include <cuda_runtime.h>
#include <cuda_fp16.h>
#include <cstdint>

#define B 2
#define S 2048
#define D 1024
#define H 16
#define DH 64
#define BS (B*S)
#define NW 4096   // 3072 qkv cols + 1024 out-proj cols

// Scratch (allocation-free rule: __device__ globals) — all fp16
__device__ __half g_Xh[BS*D];        // X converted to half
__device__ __half g_Qh[B*H*S*DH];    // [bh][s][e], pre-scaled by 1/32
__device__ __half g_Kh[B*H*S*DH];    // [bh][s][e]
__device__ __half g_Vh[B*H*DH*S];    // TRANSPOSED [bh][e][s]
__device__ __half g_Oh[BS*D];        // attention output half [b*S+s][h*DH+e]
__device__ __half g_WTh[NW*D];       // transposed weights, half

__device__ __forceinline__ uint32_t smem_u32(const void* p) {
    uint32_t a;
    asm("{ .reg .u64 t; cvta.to.shared.u64 t, %1; cvt.u32.u64 %0, t; }"
        : "=r"(a) : "l"(p));
    return a;
}
// pack(lo, hi): lo -> low 16 bits
__device__ __forceinline__ uint32_t pack_h2(float lo, float hi) {
    uint32_t r;
    asm("cvt.rn.f16x2.f32 %0, %1, %2;" : "=r"(r) : "f"(hi), "f"(lo));
    return r;
}

#define MMA_F16(c, a, b)                                                    \
    asm volatile(                                                           \
        "mma.sync.aligned.m16n8k16.row.col.f32.f16.f16.f32 "                \
        "{%0,%1,%2,%3}, {%4,%5,%6,%7}, {%8,%9}, {%0,%1,%2,%3};"             \
        : "+f"((c)[0]), "+f"((c)[1]), "+f"((c)[2]), "+f"((c)[3])            \
        : "r"((a)[0]), "r"((a)[1]), "r"((a)[2]), "r"((a)[3]),               \
          "r"((b)[0]), "r"((b)[1]))

#define CP16(dst, src) \
    asm volatile("cp.async.cg.shared.global [%0], [%1], 16;" :: "r"(dst), "l"(src))
#define CP_COMMIT() asm volatile("cp.async.commit_group;" ::: "memory")
#define CP_WAIT1()  asm volatile("cp.async.wait_group 1;" ::: "memory")
#define CP_WAIT0()  asm volatile("cp.async.wait_group 0;" ::: "memory")

// ===========================================================================
// Prep: X -> half
// ===========================================================================
__global__ void cvt_x(const float* __restrict__ X) {
    int i = (blockIdx.x * 256 + threadIdx.x) * 4;
    float4 v = *reinterpret_cast<const float4*>(X + i);
    __half2 h0 = __floats2half2_rn(v.x, v.y);
    __half2 h1 = __floats2half2_rn(v.z, v.w);
    *reinterpret_cast<__half2*>(&g_Xh[i])     = h0;
    *reinterpret_cast<__half2*>(&g_Xh[i + 2]) = h1;
}

// ===========================================================================
// Prep: weight transpose to half: g_WTh[n][d] = Wbig[d][n]
// ===========================================================================
__global__ void prep_wt(const float* __restrict__ Wq, const float* __restrict__ Wk,
                        const float* __restrict__ Wv, const float* __restrict__ Wo) {
    __shared__ float t[32][33];
    const int n0 = blockIdx.x * 32;
    const int d0 = blockIdx.y * 32;
    const int tx = threadIdx.x, ty = threadIdx.y;

    #pragma unroll
    for (int k = 0; k < 4; k++) {
        int d = d0 + ty + 8 * k;
        int n = n0 + tx;
        float v;
        if (n < 3072) {
            int z = n >> 10, h = (n >> 6) & 15, e = n & 63;
            const float* Wz = (z == 0) ? Wq : (z == 1) ? Wk : Wv;
            v = Wz[((size_t)h * D + d) * DH + e];
        } else {
            v = Wo[(size_t)d * D + (n - 3072)];
        }
        t[tx][ty + 8 * k] = v;
    }
    __syncthreads();
    #pragma unroll
    for (int k = 0; k < 4; k++) {
        int n = n0 + ty + 8 * k;
        int d = d0 + tx;
        g_WTh[(size_t)n * D + d] = __float2half_rn(t[ty + 8 * k][tx]);
    }
}

// ===========================================================================
// fp16 pipelined GEMM: C[4096, 128-block] = A[4096,1024] @ WTh^T
// BK=32, 2-stage cp.async double buffer, 8 warps (2x4), warp tile 64x32.
//   mode 0: A = g_Xh, out -> g_Qh (scaled 1/32) / g_Kh / g_Vh (transposed)
//   mode 1: A = g_Oh, out = Cout(fp32) + bias
// smem: 4 tiles x 128x40 halfs = 40960 B
// ===========================================================================
#define GTS (128*40)

__global__ __launch_bounds__(256, 2) void gemm_h(
    const float* __restrict__ bias,
    float* __restrict__ Cout,
    int nwbase, int mode)
{
    extern __shared__ __half smh[];
    const uint32_t sbase = smem_u32(smh);

    const int tid = threadIdx.x;
    const int wid = tid >> 5;
    const int lane = tid & 31;
    const int t = lane & 3;
    const int g = lane >> 2;
    const int wm = wid >> 2;
    const int wn = wid & 3;
    const int row0 = blockIdx.x * 128;
    const int n0 = blockIdx.y * 128;

    const __half* Ah = (mode == 0) ? (const __half*)g_Xh : (const __half*)g_Oh;

    auto stage = [&](int k0, int buf) {
        const uint32_t ab = sbase + (2 * buf) * GTS * 2;
        const uint32_t bb = sbase + (2 * buf + 1) * GTS * 2;
        #pragma unroll
        for (int i = 0; i < 2; i++) {
            int f = tid + i * 256;
            int m = f >> 2, seg = f & 3;
            CP16(ab + (m * 40 + seg * 8) * 2, Ah + (size_t)(row0 + m) * D + k0 + seg * 8);
            CP16(bb + (m * 40 + seg * 8) * 2, g_WTh + (size_t)(nwbase + n0 + m) * D + k0 + seg * 8);
        }
    };

    float c[4][4][4];
    #pragma unroll
    for (int mt = 0; mt < 4; mt++)
        #pragma unroll
        for (int nt = 0; nt < 4; nt++)
            #pragma unroll
            for (int q = 0; q < 4; q++) c[mt][nt][q] = 0.f;

    stage(0, 0);
    CP_COMMIT();

    for (int it = 0; it < 32; it++) {
        if (it < 31) {
            stage((it + 1) * 32, (it + 1) & 1);
            CP_COMMIT();
            CP_WAIT1();
        } else {
            CP_WAIT0();
        }
        __syncthreads();

        const __half* Af = smh + (2 * (it & 1)) * GTS;
        const __half* Bf = smh + (2 * (it & 1) + 1) * GTS;
        #pragma unroll
        for (int ks = 0; ks < 2; ks++) {
            const int kb = ks * 16;
            uint32_t a[4][4], b[4][2];
            #pragma unroll
            for (int mt = 0; mt < 4; mt++) {
                int m0 = wm * 64 + mt * 16 + g;
                a[mt][0] = *reinterpret_cast<const uint32_t*>(Af + m0 * 40 + kb + 2 * t);
                a[mt][1] = *reinterpret_cast<const uint32_t*>(Af + (m0 + 8) * 40 + kb + 2 * t);
                a[mt][2] = *reinterpret_cast<const uint32_t*>(Af + m0 * 40 + kb + 8 + 2 * t);
                a[mt][3] = *reinterpret_cast<const uint32_t*>(Af + (m0 + 8) * 40 + kb + 8 + 2 * t);
            }
            #pragma unroll
            for (int nt = 0; nt < 4; nt++) {
                int n = wn * 32 + nt * 8 + g;
                b[nt][0] = *reinterpret_cast<const uint32_t*>(Bf + n * 40 + kb + 2 * t);
                b[nt][1] = *reinterpret_cast<const uint32_t*>(Bf + n * 40 + kb + 8 + 2 * t);
            }
            #pragma unroll
            for (int mt = 0; mt < 4; mt++)
                #pragma unroll
                for (int nt = 0; nt < 4; nt++)
                    MMA_F16(c[mt][nt], a[mt], b[nt]);
        }
        __syncthreads();
    }

    // --- epilogue ---
    #pragma unroll
    for (int mt = 0; mt < 4; mt++) {
        int m_lo = row0 + wm * 64 + mt * 16 + g;
        int m_hi = m_lo + 8;
        #pragma unroll
        for (int nt = 0; nt < 4; nt++) {
            int n = n0 + wn * 32 + nt * 8 + 2 * t;
            if (mode == 0) {
                int z = n >> 10, rr = n & 1023;
                int h = rr >> 6, e0 = rr & 63;
                int bb_lo = m_lo >> 11, ss_lo = m_lo & (S - 1);
                int bb_hi = m_hi >> 11, ss_hi = m_hi & (S - 1);
                if (z == 0) {
                    *reinterpret_cast<__half2*>(
                        g_Qh + ((size_t)(bb_lo * H + h) * S + ss_lo) * DH + e0) =
                        __floats2half2_rn(c[mt][nt][0] * 0.03125f, c[mt][nt][1] * 0.03125f);
                    *reinterpret_cast<__half2*>(
                        g_Qh + ((size_t)(bb_hi * H + h) * S + ss_hi) * DH + e0) =
                        __floats2half2_rn(c[mt][nt][2] * 0.03125f, c[mt][nt][3] * 0.03125f);
                } else if (z == 1) {
                    *reinterpret_cast<__half2*>(
                        g_Kh + ((size_t)(bb_lo * H + h) * S + ss_lo) * DH + e0) =
                        __floats2half2_rn(c[mt][nt][0], c[mt][nt][1]);
                    *reinterpret_cast<__half2*>(
                        g_Kh + ((size_t)(bb_hi * H + h) * S + ss_hi) * DH + e0) =
                        __floats2half2_rn(c[mt][nt][2], c[mt][nt][3]);
                } else {
                    // V transposed: [bh][e][s]
                    __half* vb = g_Vh + ((size_t)(bb_lo * H + h) * DH + e0) * S;
                    vb[ss_lo]     = __float2half_rn(c[mt][nt][0]);
                    vb[S + ss_lo] = __float2half_rn(c[mt][nt][1]);
                    __half* vb2 = g_Vh + ((size_t)(bb_hi * H + h) * DH + e0) * S;
                    vb2[ss_hi]     = __float2half_rn(c[mt][nt][2]);
                    vb2[S + ss_hi] = __float2half_rn(c[mt][nt][3]);
                }
            } else {
                float2 bv = *reinterpret_cast<const float2*>(bias + n);
                *reinterpret_cast<float2*>(Cout + (size_t)m_lo * D + n) =
                    make_float2(c[mt][nt][0] + bv.x, c[mt][nt][1] + bv.y);
                *reinterpret_cast<float2*>(Cout + (size_t)m_hi * D + n) =
                    make_float2(c[mt][nt][2] + bv.x, c[mt][nt][3] + bv.y);
            }
        }
    }
}

// ===========================================================================
// Flash attention, fp16 mma m16n8k16, cp.async double-buffered K/V.
// CTA: 128 q-rows of one (b,h); 8 warps x 16 rows; k-tile 64.
// P: C-frag of S == A-frag of PV (fp16 layout identity) -> just f16x2 packs.
// smem: 2 x (K[64][72] + V[64][72]) halfs = 36864 B
// ===========================================================================
#define KVTH (64*72)

__global__ __launch_bounds__(256, 2) void attn_h() {
    extern __shared__ __half smh[];
    const uint32_t sbase = smem_u32(smh);

    const int qt = blockIdx.x;
    const int bh = blockIdx.y;
    const __half* Qg = g_Qh + (size_t)bh * S * DH + (size_t)qt * 128 * DH;
    const __half* Kg = g_Kh + (size_t)bh * S * DH;
    const __half* Vg = g_Vh + (size_t)bh * DH * S;   // [e][s]

    const int tid = threadIdx.x;
    const int wid = tid >> 5;
    const int lane = tid & 31;
    const int t = lane & 3;
    const int g = lane >> 2;
    const int mrow = wid * 16 + g;

    auto stage = [&](int kt, int buf) {
        const uint32_t kb = sbase + buf * (2 * KVTH) * 2;
        const uint32_t vb = kb + KVTH * 2;
        #pragma unroll
        for (int i = 0; i < 2; i++) {
            int f = tid + i * 256;
            int r = f >> 3, seg = f & 7;
            CP16(kb + (r * 72 + seg * 8) * 2, Kg + ((size_t)kt * 64 + r) * DH + seg * 8);
            CP16(vb + (r * 72 + seg * 8) * 2, Vg + (size_t)r * S + kt * 64 + seg * 8);
        }
    };

    // --- persistent Q fragments (already scaled at QKV epilogue) ---
    uint32_t qf[4][4];
    #pragma unroll
    for (int ks = 0; ks < 4; ks++) {
        qf[ks][0] = *reinterpret_cast<const uint32_t*>(Qg + (size_t)mrow * DH + 16 * ks + 2 * t);
        qf[ks][1] = *reinterpret_cast<const uint32_t*>(Qg + (size_t)(mrow + 8) * DH + 16 * ks + 2 * t);
        qf[ks][2] = *reinterpret_cast<const uint32_t*>(Qg + (size_t)mrow * DH + 16 * ks + 8 + 2 * t);
        qf[ks][3] = *reinterpret_cast<const uint32_t*>(Qg + (size_t)(mrow + 8) * DH + 16 * ks + 8 + 2 * t);
    }

    float oacc[8][4];
    #pragma unroll
    for (int nt = 0; nt < 8; nt++)
        #pragma unroll
        for (int q = 0; q < 4; q++) oacc[nt][q] = 0.f;
    float m_lo = -1e30f, m_hi = -1e30f, l_lo = 0.f, l_hi = 0.f;

    stage(0, 0);
    CP_COMMIT();

    for (int kt = 0; kt < S / 64; kt++) {
        if (kt < S / 64 - 1) {
            stage(kt + 1, (kt + 1) & 1);
            CP_COMMIT();
            CP_WAIT1();
        } else {
            CP_WAIT0();
        }
        __syncthreads();

        const __half* Kf = smh + (kt & 1) * (2 * KVTH);
        const __half* Vf = Kf + KVTH;

        // --- S = Q K^T ---
        float s[8][4];
        #pragma unroll
        for (int nt = 0; nt < 8; nt++)
            #pragma unroll
            for (int q = 0; q < 4; q++) s[nt][q] = 0.f;

        #pragma unroll
        for (int ks = 0; ks < 4; ks++) {
            #pragma unroll
            for (int nt = 0; nt < 8; nt++) {
                uint32_t b[2];
                b[0] = *reinterpret_cast<const uint32_t*>(Kf + (8 * nt + g) * 72 + 16 * ks + 2 * t);
                b[1] = *reinterpret_cast<const uint32_t*>(Kf + (8 * nt + g) * 72 + 16 * ks + 8 + 2 * t);
                MMA_F16(s[nt], qf[ks], b);
            }
        }

        // --- online softmax (rows mrow, mrow+8) ---
        float mx_lo = -1e30f, mx_hi = -1e30f;
        #pragma unroll
        for (int nt = 0; nt < 8; nt++) {
            mx_lo = fmaxf(mx_lo, fmaxf(s[nt][0], s[nt][1]));
            mx_hi = fmaxf(mx_hi, fmaxf(s[nt][2], s[nt][3]));
        }
        mx_lo = fmaxf(mx_lo, __shfl_xor_sync(0xffffffffu, mx_lo, 1));
        mx_lo = fmaxf(mx_lo, __shfl_xor_sync(0xffffffffu, mx_lo, 2));
        mx_hi = fmaxf(mx_hi, __shfl_xor_sync(0xffffffffu, mx_hi, 1));
        mx_hi = fmaxf(mx_hi, __shfl_xor_sync(0xffffffffu, mx_hi, 2));

        float mn_lo = fmaxf(m_lo, mx_lo);
        float mn_hi = fmaxf(m_hi, mx_hi);
        float corr_lo = __expf(m_lo - mn_lo);
        float corr_hi = __expf(m_hi - mn_hi);
        m_lo = mn_lo; m_hi = mn_hi;

        float rs_lo = 0.f, rs_hi = 0.f;
        #pragma unroll
        for (int nt = 0; nt < 8; nt++) {
            s[nt][0] = __expf(s[nt][0] - mn_lo);
            s[nt][1] = __expf(s[nt][1] - mn_lo);
            s[nt][2] = __expf(s[nt][2] - mn_hi);
            s[nt][3] = __expf(s[nt][3] - mn_hi);
            rs_lo += s[nt][0] + s[nt][1];
            rs_hi += s[nt][2] + s[nt][3];
        }
        rs_lo += __shfl_xor_sync(0xffffffffu, rs_lo, 1);
        rs_lo += __shfl_xor_sync(0xffffffffu, rs_lo, 2);
        rs_hi += __shfl_xor_sync(0xffffffffu, rs_hi, 1);
        rs_hi += __shfl_xor_sync(0xffffffffu, rs_hi, 2);
        l_lo = l_lo * corr_lo + rs_lo;
        l_hi = l_hi * corr_hi + rs_hi;

        #pragma unroll
        for (int nt = 0; nt < 8; nt++) {
            oacc[nt][0] *= corr_lo; oacc[nt][1] *= corr_lo;
            oacc[nt][2] *= corr_hi; oacc[nt][3] *= corr_hi;
        }

        // --- O += P @ V  (C-frag == A-frag layout for fp16: just pack) ---
        #pragma unroll
        for (int kk = 0; kk < 4; kk++) {
            uint32_t ap[4];
            ap[0] = pack_h2(s[2 * kk][0],     s[2 * kk][1]);
            ap[1] = pack_h2(s[2 * kk][2],     s[2 * kk][3]);
            ap[2] = pack_h2(s[2 * kk + 1][0], s[2 * kk + 1][1]);
            ap[3] = pack_h2(s[2 * kk + 1][2], s[2 * kk + 1][3]);
            #pragma unroll
            for (int nt = 0; nt < 8; nt++) {
                uint32_t b[2];
                b[0] = *reinterpret_cast<const uint32_t*>(Vf + (8 * nt + g) * 72 + 16 * kk + 2 * t);
                b[1] = *reinterpret_cast<const uint32_t*>(Vf + (8 * nt + g) * 72 + 16 * kk + 8 + 2 * t);
                MMA_F16(oacc[nt], ap, b);
            }
        }
        __syncthreads();
    }

    // --- epilogue: normalize, write g_Oh ---
    const float inv_lo = 1.f / l_lo;
    const float inv_hi = 1.f / l_hi;
    const int bb = bh >> 4, hh = bh & 15;
    const int row_lo = qt * 128 + wid * 16 + g;
    const int row_hi = row_lo + 8;
    #pragma unroll
    for (int nt = 0; nt < 8; nt++) {
        int e = 8 * nt + 2 * t;
        *reinterpret_cast<__half2*>(
            g_Oh + ((size_t)bb * S + row_lo) * D + hh * DH + e) =
            __floats2half2_rn(oacc[nt][0] * inv_lo, oacc[nt][1] * inv_lo);
        *reinterpret_cast<__half2*>(
            g_Oh + ((size_t)bb * S + row_hi) * D + hh * DH + e) =
            __floats2half2_rn(oacc[nt][2] * inv_hi, oacc[nt][3] * inv_hi);
    }
}

extern "C" void kernel_launch(void* const* d_in, const int* in_sizes, int n_in,
                              void* d_out, int out_size) {
    const float* X  = (const float*)d_in[0];
    const float* Wq = (const float*)d_in[1];
    const float* Wk = (const float*)d_in[2];
    const float* Wv = (const float*)d_in[3];
    const float* Wo = (const float*)d_in[4];
    const float* bo = (const float*)d_in[5];
    float* out = (float*)d_out;

    cvt_x<<<BS * D / (256 * 4), 256>>>(X);
    prep_wt<<<dim3(NW / 32, D / 32), dim3(32, 8)>>>(Wq, Wk, Wv, Wo);

    const int gemm_smem = 4 * GTS * (int)sizeof(__half);  // 40960
    cudaFuncSetAttribute(gemm_h, cudaFuncAttributeMaxDynamicSharedMemorySize, gemm_smem);
    gemm_h<<<dim3(BS / 128, 24), 256, gemm_smem>>>(nullptr, nullptr, 0, 0);

    const int attn_smem = 4 * KVTH * (int)sizeof(__half);  // 36864
    cudaFuncSetAttribute(attn_h, cudaFuncAttributeMaxDynamicSharedMemorySize, attn_smem);
    attn_h<<<dim3(S / 128, B * H), 256, attn_smem>>>();

    gemm_h<<<dim3(BS / 128, 8), 256, gemm_smem>>>(bo, out, 3072, 1);
}

// round 7
// speedup vs baseline: 6.0687x; 1.0669x over previous
#include <cuda_runtime.h>
#include <cuda_fp16.h>
#include <cstdint>

#define B 2
#define S 2048
#define D 1024
#define H 16
#define DH 64
#define BS (B*S)
#define NW 4096   // 3072 qkv cols + 1024 out-proj cols

// Scratch (allocation-free rule: __device__ globals) — all fp16
__device__ __half g_Xh[BS*D];        // X converted to half
__device__ __half g_Qh[B*H*S*DH];    // [bh][s][e], pre-scaled by log2(e)/32
__device__ __half g_Kh[B*H*S*DH];    // [bh][s][e]
__device__ __half g_Vh[B*H*DH*S];    // TRANSPOSED [bh][e][s]
__device__ __half g_Oh[BS*D];        // attention output half [b*S+s][h*DH+e]
__device__ __half g_WTh[NW*D];       // transposed weights, half

#define QSCALE 0.04508687162f   // log2(e) / 32

__device__ __forceinline__ uint32_t smem_u32(const void* p) {
    uint32_t a;
    asm("{ .reg .u64 t; cvta.to.shared.u64 t, %1; cvt.u32.u64 %0, t; }"
        : "=r"(a) : "l"(p));
    return a;
}
// pack(lo, hi): lo -> low 16 bits
__device__ __forceinline__ uint32_t pack_h2(float lo, float hi) {
    uint32_t r;
    asm("cvt.rn.f16x2.f32 %0, %1, %2;" : "=r"(r) : "f"(hi), "f"(lo));
    return r;
}

#define MMA_F16(c, a, b)                                                    \
    asm volatile(                                                           \
        "mma.sync.aligned.m16n8k16.row.col.f32.f16.f16.f32 "                \
        "{%0,%1,%2,%3}, {%4,%5,%6,%7}, {%8,%9}, {%0,%1,%2,%3};"             \
        : "+f"((c)[0]), "+f"((c)[1]), "+f"((c)[2]), "+f"((c)[3])            \
        : "r"((a)[0]), "r"((a)[1]), "r"((a)[2]), "r"((a)[3]),               \
          "r"((b)[0]), "r"((b)[1]))

#define LDSM4(r0, r1, r2, r3, addr)                                         \
    asm volatile("ldmatrix.sync.aligned.m8n8.x4.shared.b16 {%0,%1,%2,%3}, [%4];" \
        : "=r"(r0), "=r"(r1), "=r"(r2), "=r"(r3) : "r"(addr))

#define CP16(dst, src) \
    asm volatile("cp.async.cg.shared.global [%0], [%1], 16;" :: "r"(dst), "l"(src))
#define CP_COMMIT() asm volatile("cp.async.commit_group;" ::: "memory")
#define CP_WAIT1()  asm volatile("cp.async.wait_group 1;" ::: "memory")
#define CP_WAIT0()  asm volatile("cp.async.wait_group 0;" ::: "memory")

// ===========================================================================
// Prep: X -> half
// ===========================================================================
__global__ void cvt_x(const float* __restrict__ X) {
    int i = (blockIdx.x * 256 + threadIdx.x) * 4;
    float4 v = *reinterpret_cast<const float4*>(X + i);
    *reinterpret_cast<__half2*>(&g_Xh[i])     = __floats2half2_rn(v.x, v.y);
    *reinterpret_cast<__half2*>(&g_Xh[i + 2]) = __floats2half2_rn(v.z, v.w);
}

// ===========================================================================
// Prep: weight transpose to half: g_WTh[n][d] = Wbig[d][n]
// ===========================================================================
__global__ void prep_wt(const float* __restrict__ Wq, const float* __restrict__ Wk,
                        const float* __restrict__ Wv, const float* __restrict__ Wo) {
    __shared__ float t[32][33];
    const int n0 = blockIdx.x * 32;
    const int d0 = blockIdx.y * 32;
    const int tx = threadIdx.x, ty = threadIdx.y;

    #pragma unroll
    for (int k = 0; k < 4; k++) {
        int d = d0 + ty + 8 * k;
        int n = n0 + tx;
        float v;
        if (n < 3072) {
            int z = n >> 10, h = (n >> 6) & 15, e = n & 63;
            const float* Wz = (z == 0) ? Wq : (z == 1) ? Wk : Wv;
            v = Wz[((size_t)h * D + d) * DH + e];
        } else {
            v = Wo[(size_t)d * D + (n - 3072)];
        }
        t[tx][ty + 8 * k] = v;
    }
    __syncthreads();
    #pragma unroll
    for (int k = 0; k < 4; k++) {
        int n = n0 + ty + 8 * k;
        int d = d0 + tx;
        g_WTh[(size_t)n * D + d] = __float2half_rn(t[ty + 8 * k][tx]);
    }
}

// ===========================================================================
// fp16 pipelined GEMM with ldmatrix fragment loads.
// BK=32, 2-stage cp.async double buffer, 8 warps (2x4), warp tile 64x32.
//   mode 0: A = g_Xh, out -> g_Qh (scaled log2e/32) / g_Kh / g_Vh (transposed)
//   mode 1: A = g_Oh, out = Cout(fp32) + bias
// smem: 4 tiles x 128x40 halfs = 40960 B
// ===========================================================================
#define GTS (128*40)

__global__ __launch_bounds__(256, 2) void gemm_h(
    const float* __restrict__ bias,
    float* __restrict__ Cout,
    int nwbase, int mode)
{
    extern __shared__ __half smh[];
    const uint32_t sbase = smem_u32(smh);

    const int tid = threadIdx.x;
    const int wid = tid >> 5;
    const int lane = tid & 31;
    const int t = lane & 3;
    const int g = lane >> 2;
    const int wm = wid >> 2;
    const int wn = wid & 3;
    const int row0 = blockIdx.x * 128;
    const int n0 = blockIdx.y * 128;

    // ldmatrix per-lane address components
    const int arow = ((lane & 8) ? 8 : 0) + (lane & 7);   // A: mats {rl,rh,rl,rh}, k {lo,lo,hi,hi}
    const int akoff = (lane >= 16) ? 8 : 0;
    const int brow = ((lane >= 16) ? 8 : 0) + (lane & 7); // B: mats {nl,nl,nh,nh}, k {lo,hi,lo,hi}
    const int bkoff = (lane & 8) ? 8 : 0;

    const __half* Ah = (mode == 0) ? (const __half*)g_Xh : (const __half*)g_Oh;

    auto stage = [&](int k0, int buf) {
        const uint32_t ab = sbase + (2 * buf) * GTS * 2;
        const uint32_t bb = sbase + (2 * buf + 1) * GTS * 2;
        #pragma unroll
        for (int i = 0; i < 2; i++) {
            int f = tid + i * 256;
            int m = f >> 2, seg = f & 3;
            CP16(ab + (m * 40 + seg * 8) * 2, Ah + (size_t)(row0 + m) * D + k0 + seg * 8);
            CP16(bb + (m * 40 + seg * 8) * 2, g_WTh + (size_t)(nwbase + n0 + m) * D + k0 + seg * 8);
        }
    };

    float c[4][4][4];
    #pragma unroll
    for (int mt = 0; mt < 4; mt++)
        #pragma unroll
        for (int nt = 0; nt < 4; nt++)
            #pragma unroll
            for (int q = 0; q < 4; q++) c[mt][nt][q] = 0.f;

    stage(0, 0);
    CP_COMMIT();

    for (int it = 0; it < 32; it++) {
        if (it < 31) {
            stage((it + 1) * 32, (it + 1) & 1);
            CP_COMMIT();
            CP_WAIT1();
        } else {
            CP_WAIT0();
        }
        __syncthreads();

        const uint32_t Afb = sbase + (2 * (it & 1)) * GTS * 2;
        const uint32_t Bfb = sbase + (2 * (it & 1) + 1) * GTS * 2;
        #pragma unroll
        for (int ks = 0; ks < 2; ks++) {
            const int kb = ks * 16;
            uint32_t a[4][4], b[4][2];
            #pragma unroll
            for (int mt = 0; mt < 4; mt++) {
                int r = wm * 64 + mt * 16 + arow;
                LDSM4(a[mt][0], a[mt][1], a[mt][2], a[mt][3],
                      Afb + (r * 40 + kb + akoff) * 2);
            }
            #pragma unroll
            for (int np = 0; np < 2; np++) {
                int r = wn * 32 + np * 16 + brow;
                LDSM4(b[2 * np][0], b[2 * np][1], b[2 * np + 1][0], b[2 * np + 1][1],
                      Bfb + (r * 40 + kb + bkoff) * 2);
            }
            #pragma unroll
            for (int mt = 0; mt < 4; mt++)
                #pragma unroll
                for (int nt = 0; nt < 4; nt++)
                    MMA_F16(c[mt][nt], a[mt], b[nt]);
        }
        __syncthreads();
    }

    // --- epilogue ---
    #pragma unroll
    for (int mt = 0; mt < 4; mt++) {
        int m_lo = row0 + wm * 64 + mt * 16 + g;
        int m_hi = m_lo + 8;
        #pragma unroll
        for (int nt = 0; nt < 4; nt++) {
            int n = n0 + wn * 32 + nt * 8 + 2 * t;
            if (mode == 0) {
                int z = n >> 10, rr = n & 1023;
                int h = rr >> 6, e0 = rr & 63;
                int bb_lo = m_lo >> 11, ss_lo = m_lo & (S - 1);
                int bb_hi = m_hi >> 11, ss_hi = m_hi & (S - 1);
                if (z == 0) {
                    *reinterpret_cast<__half2*>(
                        g_Qh + ((size_t)(bb_lo * H + h) * S + ss_lo) * DH + e0) =
                        __floats2half2_rn(c[mt][nt][0] * QSCALE, c[mt][nt][1] * QSCALE);
                    *reinterpret_cast<__half2*>(
                        g_Qh + ((size_t)(bb_hi * H + h) * S + ss_hi) * DH + e0) =
                        __floats2half2_rn(c[mt][nt][2] * QSCALE, c[mt][nt][3] * QSCALE);
                } else if (z == 1) {
                    *reinterpret_cast<__half2*>(
                        g_Kh + ((size_t)(bb_lo * H + h) * S + ss_lo) * DH + e0) =
                        __floats2half2_rn(c[mt][nt][0], c[mt][nt][1]);
                    *reinterpret_cast<__half2*>(
                        g_Kh + ((size_t)(bb_hi * H + h) * S + ss_hi) * DH + e0) =
                        __floats2half2_rn(c[mt][nt][2], c[mt][nt][3]);
                } else {
                    __half* vb = g_Vh + ((size_t)(bb_lo * H + h) * DH + e0) * S;
                    vb[ss_lo]     = __float2half_rn(c[mt][nt][0]);
                    vb[S + ss_lo] = __float2half_rn(c[mt][nt][1]);
                    __half* vb2 = g_Vh + ((size_t)(bb_hi * H + h) * DH + e0) * S;
                    vb2[ss_hi]     = __float2half_rn(c[mt][nt][2]);
                    vb2[S + ss_hi] = __float2half_rn(c[mt][nt][3]);
                }
            } else {
                float2 bv = *reinterpret_cast<const float2*>(bias + n);
                *reinterpret_cast<float2*>(Cout + (size_t)m_lo * D + n) =
                    make_float2(c[mt][nt][0] + bv.x, c[mt][nt][1] + bv.y);
                *reinterpret_cast<float2*>(Cout + (size_t)m_hi * D + n) =
                    make_float2(c[mt][nt][2] + bv.x, c[mt][nt][3] + bv.y);
            }
        }
    }
}

// ===========================================================================
// Flash attention, fp16 mma + ldmatrix, cp.async double-buffered K/V.
// CTA: 128 q-rows of one (b,h); 8 warps x 16 rows; k-tile 64.
// exp2-domain softmax (Q pre-scaled by log2e/32).
// smem: 2 x (K[64][72] + V[64][72]) halfs = 36864 B
// ===========================================================================
#define KVTH (64*72)

__global__ __launch_bounds__(256, 2) void attn_h() {
    extern __shared__ __half smh[];
    const uint32_t sbase = smem_u32(smh);

    const int qt = blockIdx.x;
    const int bh = blockIdx.y;
    const __half* Qg = g_Qh + (size_t)bh * S * DH + (size_t)qt * 128 * DH;
    const __half* Kg = g_Kh + (size_t)bh * S * DH;
    const __half* Vg = g_Vh + (size_t)bh * DH * S;   // [e][s]

    const int tid = threadIdx.x;
    const int wid = tid >> 5;
    const int lane = tid & 31;
    const int t = lane & 3;
    const int g = lane >> 2;
    const int mrow = wid * 16 + g;

    // ldmatrix B-operand lane addressing (mats: {n-lo,k-lo},{n-lo,k-hi},{n-hi,k-lo},{n-hi,k-hi})
    const int brow = ((lane >= 16) ? 8 : 0) + (lane & 7);
    const int bkoff = (lane & 8) ? 8 : 0;

    auto stage = [&](int kt, int buf) {
        const uint32_t kb = sbase + buf * (2 * KVTH) * 2;
        const uint32_t vb = kb + KVTH * 2;
        #pragma unroll
        for (int i = 0; i < 2; i++) {
            int f = tid + i * 256;
            int r = f >> 3, seg = f & 7;
            CP16(kb + (r * 72 + seg * 8) * 2, Kg + ((size_t)kt * 64 + r) * DH + seg * 8);
            CP16(vb + (r * 72 + seg * 8) * 2, Vg + (size_t)r * S + kt * 64 + seg * 8);
        }
    };

    // --- persistent Q fragments (pre-scaled by log2e/32 at QKV epilogue) ---
    uint32_t qf[4][4];
    #pragma unroll
    for (int ks = 0; ks < 4; ks++) {
        qf[ks][0] = *reinterpret_cast<const uint32_t*>(Qg + (size_t)mrow * DH + 16 * ks + 2 * t);
        qf[ks][1] = *reinterpret_cast<const uint32_t*>(Qg + (size_t)(mrow + 8) * DH + 16 * ks + 2 * t);
        qf[ks][2] = *reinterpret_cast<const uint32_t*>(Qg + (size_t)mrow * DH + 16 * ks + 8 + 2 * t);
        qf[ks][3] = *reinterpret_cast<const uint32_t*>(Qg + (size_t)(mrow + 8) * DH + 16 * ks + 8 + 2 * t);
    }

    float oacc[8][4];
    #pragma unroll
    for (int nt = 0; nt < 8; nt++)
        #pragma unroll
        for (int q = 0; q < 4; q++) oacc[nt][q] = 0.f;
    float m_lo = -1e30f, m_hi = -1e30f, l_lo = 0.f, l_hi = 0.f;

    stage(0, 0);
    CP_COMMIT();

    for (int kt = 0; kt < S / 64; kt++) {
        if (kt < S / 64 - 1) {
            stage(kt + 1, (kt + 1) & 1);
            CP_COMMIT();
            CP_WAIT1();
        } else {
            CP_WAIT0();
        }
        __syncthreads();

        const uint32_t Kfb = sbase + (kt & 1) * (2 * KVTH) * 2;
        const uint32_t Vfb = Kfb + KVTH * 2;

        // --- S = Q K^T ---
        float s[8][4];
        #pragma unroll
        for (int nt = 0; nt < 8; nt++)
            #pragma unroll
            for (int q = 0; q < 4; q++) s[nt][q] = 0.f;

        #pragma unroll
        for (int ks = 0; ks < 4; ks++) {
            #pragma unroll
            for (int np = 0; np < 4; np++) {
                uint32_t b0, b1, b2, b3;
                LDSM4(b0, b1, b2, b3,
                      Kfb + ((16 * np + brow) * 72 + 16 * ks + bkoff) * 2);
                uint32_t be[2] = {b0, b1}, bo[2] = {b2, b3};
                MMA_F16(s[2 * np], qf[ks], be);
                MMA_F16(s[2 * np + 1], qf[ks], bo);
            }
        }

        // --- online softmax, exp2 domain (rows mrow, mrow+8) ---
        float mx_lo = -1e30f, mx_hi = -1e30f;
        #pragma unroll
        for (int nt = 0; nt < 8; nt++) {
            mx_lo = fmaxf(mx_lo, fmaxf(s[nt][0], s[nt][1]));
            mx_hi = fmaxf(mx_hi, fmaxf(s[nt][2], s[nt][3]));
        }
        mx_lo = fmaxf(mx_lo, __shfl_xor_sync(0xffffffffu, mx_lo, 1));
        mx_lo = fmaxf(mx_lo, __shfl_xor_sync(0xffffffffu, mx_lo, 2));
        mx_hi = fmaxf(mx_hi, __shfl_xor_sync(0xffffffffu, mx_hi, 1));
        mx_hi = fmaxf(mx_hi, __shfl_xor_sync(0xffffffffu, mx_hi, 2));

        float mn_lo = fmaxf(m_lo, mx_lo);
        float mn_hi = fmaxf(m_hi, mx_hi);
        float corr_lo = exp2f(m_lo - mn_lo);
        float corr_hi = exp2f(m_hi - mn_hi);
        m_lo = mn_lo; m_hi = mn_hi;

        float rs_lo = 0.f, rs_hi = 0.f;
        #pragma unroll
        for (int nt = 0; nt < 8; nt++) {
            s[nt][0] = exp2f(s[nt][0] - mn_lo);
            s[nt][1] = exp2f(s[nt][1] - mn_lo);
            s[nt][2] = exp2f(s[nt][2] - mn_hi);
            s[nt][3] = exp2f(s[nt][3] - mn_hi);
            rs_lo += s[nt][0] + s[nt][1];
            rs_hi += s[nt][2] + s[nt][3];
        }
        rs_lo += __shfl_xor_sync(0xffffffffu, rs_lo, 1);
        rs_lo += __shfl_xor_sync(0xffffffffu, rs_lo, 2);
        rs_hi += __shfl_xor_sync(0xffffffffu, rs_hi, 1);
        rs_hi += __shfl_xor_sync(0xffffffffu, rs_hi, 2);
        l_lo = l_lo * corr_lo + rs_lo;
        l_hi = l_hi * corr_hi + rs_hi;

        #pragma unroll
        for (int nt = 0; nt < 8; nt++) {
            oacc[nt][0] *= corr_lo; oacc[nt][1] *= corr_lo;
            oacc[nt][2] *= corr_hi; oacc[nt][3] *= corr_hi;
        }

        // --- O += P @ V  (C-frag == A-frag layout for fp16) ---
        #pragma unroll
        for (int kk = 0; kk < 4; kk++) {
            uint32_t ap[4];
            ap[0] = pack_h2(s[2 * kk][0],     s[2 * kk][1]);
            ap[1] = pack_h2(s[2 * kk][2],     s[2 * kk][3]);
            ap[2] = pack_h2(s[2 * kk + 1][0], s[2 * kk + 1][1]);
            ap[3] = pack_h2(s[2 * kk + 1][2], s[2 * kk + 1][3]);
            #pragma unroll
            for (int np = 0; np < 4; np++) {
                uint32_t b0, b1, b2, b3;
                LDSM4(b0, b1, b2, b3,
                      Vfb + ((16 * np + brow) * 72 + 16 * kk + bkoff) * 2);
                uint32_t be[2] = {b0, b1}, bo[2] = {b2, b3};
                MMA_F16(oacc[2 * np], ap, be);
                MMA_F16(oacc[2 * np + 1], ap, bo);
            }
        }
        __syncthreads();
    }

    // --- epilogue: normalize, write g_Oh ---
    const float inv_lo = 1.f / l_lo;
    const float inv_hi = 1.f / l_hi;
    const int bb = bh >> 4, hh = bh & 15;
    const int row_lo = qt * 128 + wid * 16 + g;
    const int row_hi = row_lo + 8;
    #pragma unroll
    for (int nt = 0; nt < 8; nt++) {
        int e = 8 * nt + 2 * t;
        *reinterpret_cast<__half2*>(
            g_Oh + ((size_t)bb * S + row_lo) * D + hh * DH + e) =
            __floats2half2_rn(oacc[nt][0] * inv_lo, oacc[nt][1] * inv_lo);
        *reinterpret_cast<__half2*>(
            g_Oh + ((size_t)bb * S + row_hi) * D + hh * DH + e) =
            __floats2half2_rn(oacc[nt][2] * inv_hi, oacc[nt][3] * inv_hi);
    }
}

extern "C" void kernel_launch(void* const* d_in, const int* in_sizes, int n_in,
                              void* d_out, int out_size) {
    const float* X  = (const float*)d_in[0];
    const float* Wq = (const float*)d_in[1];
    const float* Wk = (const float*)d_in[2];
    const float* Wv = (const float*)d_in[3];
    const float* Wo = (const float*)d_in[4];
    const float* bo = (const float*)d_in[5];
    float* out = (float*)d_out;

    cvt_x<<<BS * D / (256 * 4), 256>>>(X);
    prep_wt<<<dim3(NW / 32, D / 32), dim3(32, 8)>>>(Wq, Wk, Wv, Wo);

    const int gemm_smem = 4 * GTS * (int)sizeof(__half);  // 40960
    cudaFuncSetAttribute(gemm_h, cudaFuncAttributeMaxDynamicSharedMemorySize, gemm_smem);
    gemm_h<<<dim3(BS / 128, 24), 256, gemm_smem>>>(nullptr, nullptr, 0, 0);

    const int attn_smem = 4 * KVTH * (int)sizeof(__half);  // 36864
    cudaFuncSetAttribute(attn_h, cudaFuncAttributeMaxDynamicSharedMemorySize, attn_smem);
    attn_h<<<dim3(S / 128, B * H), 256, attn_smem>>>();

    gemm_h<<<dim3(BS / 128, 8), 256, gemm_smem>>>(bo, out, 3072, 1);
}